// round 13
// baseline (speedup 1.0000x reference)
#include <cuda_runtime.h>
#include <cuda_fp16.h>
#include <cstdint>

#define N_NODES 50000
#define N_EDGES 400000
#define H 128
#define DEPTH 8
#define TILE_N 64      // nodes per block tile
#define NTHREADS 512
#define NBLOCKS 148
#define ASTH 136       // activation smem row stride in halves (128 + 8)
#define ASTF 132       // fp32 h epilogue stride (128 + 4)
#define WSTH 40        // weight slab row stride in halves (32 + 8)

// ---------------- device scratch (no allocation allowed) ----------------
__device__ float  g_p1[N_NODES];
__device__ float  g_p2[N_NODES];
__device__ int    g_node_list[N_NODES];
__device__ int    g_deg[N_NODES];
__device__ int    g_row[N_NODES + 1];
__device__ int    g_cur[N_NODES];
__device__ int    g_es[N_EDGES];          // edge srcs grouped by dst (CSR)
__device__ int    g_cnts[32];
__device__ int    g_node_off[DEPTH + 1];
__device__ unsigned g_bar_count;          // cumulative grid-barrier counter
__device__ unsigned g_base;               // snapshot at launch (k_setup)
// fused weights, ROW-major [384 rows][128 k], fp16
__device__ __half g_WbigH[384 * 128];     // W_ih[:,:128] @ W_msg
__device__ __half g_WhhH[384 * 128];
__device__ float  g_bbig[384];            // b_ih + W_ih[:,:128] @ b_msg

// smem byte offsets for k_all dynamic smem (phase D)
#define SMB_WSA0  0                 // 128*40 halves = 10240 B
#define SMB_WSA1  10240
#define SMB_WSB0  20480
#define SMB_WSB1  30720
#define SMB_XS    40960             // 64*136 halves = 17408 B
#define SMB_HS    58368             // 17408 B
#define SMB_HSF   75776             // 64*132 fp32 = 33792 B
#define SMB_NT    109568            // 3*384 fp32 = 4608 B
#define SMB_BB    114176            // 1536 B
#define SMB_BH    115712            // 1536 B
#define SMB_SP1   117248            // 256 B
#define SMB_SP2   117504
#define SMB_SNODE 117760
#define SMB_SACT  118016
#define SMB_SRD   118272
#define SMB_STYPE 118528
#define SMB_TOTAL 118784

__device__ __forceinline__ int clamp_lvl(int l) { return l < 0 ? 0 : (l > 7 ? 7 : l); }
__device__ __forceinline__ float sig_(float x) { return 1.0f / (1.0f + __expf(-x)); }
__device__ __forceinline__ float tanh_(float x) { return 2.0f / (1.0f + __expf(-2.0f * x)) - 1.0f; }

// software grid barrier: all 148 blocks co-resident (116KB smem -> 1 block/SM).
// cumulative counter + per-launch base snapshot (set by k_setup) keeps replays clean.
__device__ __forceinline__ void gbar(int nb, int t) {
    __syncthreads();
    if (t == 0) {
        __threadfence();
        atomicAdd(&g_bar_count, 1u);
        unsigned target = g_base + (unsigned)nb * (unsigned)NBLOCKS;
        unsigned cur;
        do {
            asm volatile("ld.acquire.gpu.u32 %0, [%1];"
                         : "=r"(cur) : "l"(&g_bar_count) : "memory");
        } while ((int)(cur - target) < 0);
    }
    __syncthreads();
}

// ---------------- setup: fuse W_big + convert Whh + zero deg/cnts + base snapshot --
__global__ __launch_bounds__(128) void k_setup(const float* __restrict__ Wih,
                                               const float* __restrict__ Wmsg,
                                               const float* __restrict__ bih,
                                               const float* __restrict__ bmsg,
                                               const float* __restrict__ Whh) {
    int r = blockIdx.x;        // 0..383
    int m = threadIdx.x;       // 0..127
    if (r == 0 && m == 0) g_base = g_bar_count;   // snapshot for this launch
    __shared__ float wr[128];
    wr[m] = Wih[r * 131 + m];
    __syncthreads();
    float s = 0.f;
#pragma unroll 8
    for (int j = 0; j < 128; j++) s += wr[j] * Wmsg[j * 128 + m];
    g_WbigH[r * 128 + m] = __float2half(s);
    if (m == 0) {
        float b = bih[r];
        for (int j = 0; j < 128; j++) b += wr[j] * bmsg[j];
        g_bbig[r] = b;
    }
    int gid = r * 128 + m;                       // 0..49151
    g_WhhH[gid] = __float2half(Whh[gid]);
    for (int idx = gid; idx < N_NODES; idx += 384 * 128) g_deg[idx] = 0;
    if (gid < 32) g_cnts[gid] = 0;
}

// ---------------- weight slab prefetch (phase D GEMM) ----------------
__device__ __forceinline__ void issue_dual(int rowBase, int k0,
                                           __half* bufA, __half* bufB, int t) {
    int row = t >> 2, seg = (t & 3) << 3;       // 512 threads cover 128 rows x 4 segs
    unsigned da = (unsigned)__cvta_generic_to_shared(bufA + row * WSTH + seg);
    const __half* sa = g_WbigH + (size_t)(rowBase + row) * 128 + k0 + seg;
    asm volatile("cp.async.cg.shared.global [%0],[%1],16;"
                 :: "r"(da), "l"(sa) : "memory");
    unsigned db = (unsigned)__cvta_generic_to_shared(bufB + row * WSTH + seg);
    const __half* sb = g_WhhH + (size_t)(rowBase + row) * 128 + k0 + seg;
    asm volatile("cp.async.cg.shared.global [%0],[%1],16;"
                 :: "r"(db), "l"(sb) : "memory");
}

// dx += Wbig-chunk @ xs^T and dh += Whh-chunk @ hs^T, pipelined.
__device__ __forceinline__ void mma_dual(float (&dx)[4][4], float (&dh)[4][4],
                                         int rowBase,
                                         const __half* xs, const __half* hs,
                                         __half* wsA0, __half* wsA1,
                                         __half* wsB0, __half* wsB1,
                                         int m0, int nw32, int grp, int t4, int t) {
    __syncthreads();
    issue_dual(rowBase, 0, wsA0, wsB0, t);
    asm volatile("cp.async.commit_group;" ::: "memory");
    const unsigned* xu = (const unsigned*)xs;
    const unsigned* hu = (const unsigned*)hs;
#pragma unroll
    for (int s = 0; s < 4; s++) {
        asm volatile("cp.async.wait_group 0;" ::: "memory");
        __syncthreads();
        if (s < 3) {
            issue_dual(rowBase, (s + 1) << 5,
                       (s & 1) ? wsA0 : wsA1, (s & 1) ? wsB0 : wsB1, t);
            asm volatile("cp.async.commit_group;" ::: "memory");
        }
        const unsigned* ba = (const unsigned*)((s & 1) ? wsA1 : wsA0);
        const unsigned* bb = (const unsigned*)((s & 1) ? wsB1 : wsB0);
#pragma unroll
        for (int kstep = 0; kstep < 2; kstep++) {
            int aw = (m0 + grp) * (ASTH / 2) + (s << 4) + (kstep << 3) + t4;
            unsigned xa0 = xu[aw];
            unsigned xa1 = xu[aw + 8 * (ASTH / 2)];
            unsigned xa2 = xu[aw + 4];
            unsigned xa3 = xu[aw + 4 + 8 * (ASTH / 2)];
            unsigned ha0 = hu[aw];
            unsigned ha1 = hu[aw + 8 * (ASTH / 2)];
            unsigned ha2 = hu[aw + 4];
            unsigned ha3 = hu[aw + 4 + 8 * (ASTH / 2)];
#pragma unroll
            for (int f = 0; f < 4; f++) {
                int bw = (nw32 + (f << 3) + grp) * (WSTH / 2) + (kstep << 3) + t4;
                unsigned b0 = ba[bw];
                unsigned b1 = ba[bw + 4];
                asm volatile(
                    "mma.sync.aligned.m16n8k16.row.col.f32.f16.f16.f32 "
                    "{%0,%1,%2,%3},{%4,%5,%6,%7},{%8,%9},{%0,%1,%2,%3};"
                    : "+f"(dx[f][0]), "+f"(dx[f][1]), "+f"(dx[f][2]), "+f"(dx[f][3])
                    : "r"(xa0), "r"(xa1), "r"(xa2), "r"(xa3), "r"(b0), "r"(b1));
                unsigned c0 = bb[bw];
                unsigned c1 = bb[bw + 4];
                asm volatile(
                    "mma.sync.aligned.m16n8k16.row.col.f32.f16.f16.f32 "
                    "{%0,%1,%2,%3},{%4,%5,%6,%7},{%8,%9},{%0,%1,%2,%3};"
                    : "+f"(dh[f][0]), "+f"(dh[f][1]), "+f"(dh[f][2]), "+f"(dh[f][3])
                    : "r"(ha0), "r"(ha1), "r"(ha2), "r"(ha3), "r"(c0), "r"(c1));
            }
        }
    }
}

// ---------------- the persistent mega-kernel ----------------
__global__ __launch_bounds__(NTHREADS, 1) void k_all(
    float* __restrict__ h, const float* __restrict__ ne,
    const float* __restrict__ node_type,
    const float* __restrict__ Wattn, const float* __restrict__ b_attn,
    const float* __restrict__ Wih, const float* __restrict__ bhh,
    const int* __restrict__ esrc, const int* __restrict__ edst,
    const int* __restrict__ fnl) {
    extern __shared__ __align__(16) char smb[];
    __half* wsA0 = (__half*)(smb + SMB_WSA0);
    __half* wsA1 = (__half*)(smb + SMB_WSA1);
    __half* wsB0 = (__half*)(smb + SMB_WSB0);
    __half* wsB1 = (__half*)(smb + SMB_WSB1);
    __half* xs   = (__half*)(smb + SMB_XS);
    __half* hs   = (__half*)(smb + SMB_HS);
    float*  hsf  = (float*)(smb + SMB_HSF);
    float*  smnt = (float*)(smb + SMB_NT);
    float*  sbb  = (float*)(smb + SMB_BB);
    float*  sbh  = (float*)(smb + SMB_BH);
    float*  sp1  = (float*)(smb + SMB_SP1);
    float*  sp2  = (float*)(smb + SMB_SP2);
    int*    snode = (int*)(smb + SMB_SNODE);
    float*  sact  = (float*)(smb + SMB_SACT);
    float*  srd   = (float*)(smb + SMB_SRD);
    int*    stype = (int*)(smb + SMB_STYPE);

    int t = threadIdx.x;
    int lane = t & 31;
    int warp = t >> 5;                // 0..15
    int gtid = blockIdx.x * NTHREADS + t;
    int gstride = NBLOCKS * NTHREADS;

    // ---- Phase A: degree count + level histogram ----
    {
        __shared__ int sc[8];
        if (t < 8) sc[t] = 0;
        __syncthreads();
        for (int i = gtid; i < N_EDGES; i += gstride)
            atomicAdd(&g_deg[__ldg(&edst[i])], 1);
        for (int i = gtid; i < N_NODES; i += gstride)
            atomicAdd(&sc[clamp_lvl(__ldg(&fnl[i]))], 1);
        __syncthreads();
        if (t < 8 && sc[t] > 0) atomicAdd(&g_cnts[t], sc[t]);
    }
    gbar(1, t);

    // ---- Phase B: block 0 scans levels + degrees ----
    if (blockIdx.x == 0) {
        __shared__ int wsum2[16];
        if (t == 0) {
            int no = 0;
            for (int l = 0; l < 8; l++) { g_node_off[l] = no; no += g_cnts[l]; }
            g_node_off[8] = no;
            for (int l = 0; l < 8; l++) g_cnts[16 + l] = g_node_off[l];
        }
        const int SP = 98;                        // 512*98 >= 50000
        int base = t * SP;
        int s = 0;
        for (int j = 0; j < SP; j++) {
            int idx = base + j;
            if (idx < N_NODES) s += g_deg[idx];
        }
        int v = s;
#pragma unroll
        for (int off = 1; off < 32; off <<= 1) {
            int n = __shfl_up_sync(0xffffffffu, v, off);
            if (lane >= off) v += n;
        }
        if (lane == 31) wsum2[warp] = v;
        __syncthreads();
        if (warp == 0) {
            int wv = (lane < 16) ? wsum2[lane] : 0;
#pragma unroll
            for (int off = 1; off < 32; off <<= 1) {
                int n = __shfl_up_sync(0xffffffffu, wv, off);
                if (lane >= off) wv += n;
            }
            if (lane < 16) wsum2[lane] = wv;
        }
        __syncthreads();
        int run = v - s + (warp > 0 ? wsum2[warp - 1] : 0);
        for (int j = 0; j < SP; j++) {
            int idx = base + j;
            if (idx < N_NODES) {
                g_row[idx] = run;
                g_cur[idx] = run;
                run += g_deg[idx];
            }
        }
        if (t == NTHREADS - 1) g_row[N_NODES] = run;
    }
    gbar(2, t);

    // ---- Phase C: node scatter + CSR edge fill + init h/p1/p2 ----
    {
        __shared__ int scnt[8];
        __shared__ int sbase[8];
        if (t < 8) scnt[t] = 0;
        __syncthreads();
        int i = gtid;                  // 75776 threads >= 50000 nodes: single chunk
        int key = -1, lp = 0;
        if (i < N_NODES) {
            key = clamp_lvl(__ldg(&fnl[i]));
            lp = atomicAdd(&scnt[key], 1);
        }
        __syncthreads();
        if (t < 8 && scnt[t] > 0) sbase[t] = atomicAdd(&g_cnts[16 + t], scnt[t]);
        __syncthreads();
        if (key >= 0) g_node_list[sbase[key] + lp] = i;

        for (int e = gtid; e < N_EDGES; e += gstride) {
            int d = __ldg(&edst[e]);
            int pos = atomicAdd(&g_cur[d], 1);
            g_es[pos] = __ldg(&esrc[e]);
        }

        // init h = ne, p1/p2 projections (warp per node)
        float4 a1 = *(const float4*)&Wattn[lane * 4];
        float4 a2 = *(const float4*)&Wattn[H + lane * 4];
        int gw = blockIdx.x * 16 + warp;
        int nwr = NBLOCKS * 16;
        for (int n = gw; n < N_NODES; n += nwr) {
            float4 v = *(const float4*)&ne[(size_t)n * H + lane * 4];
            *(float4*)&h[(size_t)n * H + lane * 4] = v;
            float s1 = v.x * a1.x + v.y * a1.y + v.z * a1.z + v.w * a1.w;
            float s2 = v.x * a2.x + v.y * a2.y + v.z * a2.z + v.w * a2.w;
#pragma unroll
            for (int off = 16; off; off >>= 1) {
                s1 += __shfl_xor_sync(0xffffffffu, s1, off);
                s2 += __shfl_xor_sync(0xffffffffu, s2, off);
            }
            if (lane == 0) { g_p1[n] = s1; g_p2[n] = s2; }
        }
    }
    gbar(3, t);

    // ---- Phase D: 7 fused gather+GRU levels ----
    int grp = lane >> 2;              // 0..7
    int t4 = lane & 3;                // 0..3
    int m0 = (warp & 3) << 4;         // node base within tile
    int nw32 = (warp >> 2) << 5;      // row base: 0,32,64,96
    float battn = __ldg(b_attn);

    // stage constants ONCE
    for (int idx = t; idx < 1152; idx += NTHREADS) {
        int c = idx % 3, r = idx / 3;
        smnt[c * 384 + r] = Wih[r * 131 + 128 + c];
    }
    for (int idx = t; idx < 384; idx += NTHREADS) {
        sbb[idx] = g_bbig[idx];
        sbh[idx] = bhh[idx];
    }

    for (int level = 1; level < DEPTH; level++) {
        int start = g_node_off[level], end = g_node_off[level + 1];
        int cnt = end - start;
        int ntiles = (cnt + TILE_N - 1) / TILE_N;

        for (int tile = blockIdx.x; tile < ntiles; tile += NBLOCKS) {
            __syncthreads();          // constants/prior tile done
            if (t < TILE_N) {
                int slot = start + tile * TILE_N + t;
                int node = -1, ty = 0;
                if (slot < end) {
                    node = g_node_list[slot];
                    float n1 = node_type[(size_t)node * 3 + 1];
                    float n2 = node_type[(size_t)node * 3 + 2];
                    ty = n1 > 0.5f ? 1 : (n2 > 0.5f ? 2 : 0);
                }
                snode[t] = node; stype[t] = ty;
                sp1[t] = 0.f; sp2[t] = 0.f;
            }
            __syncthreads();

            // fused aggregation + staging: warp w handles nodes 4w..4w+3
#pragma unroll
            for (int j = 0; j < 4; j++) {
                int n = (warp << 2) | j;
                int nodeRaw = snode[n];
                bool valid = nodeRaw >= 0;
                int node = valid ? nodeRaw : 0;
                int r0 = g_row[node], r1 = g_row[node + 1];
                float p2d = g_p2[node];
                float denom = 0.f;
                float4 acc = make_float4(0.f, 0.f, 0.f, 0.f);
                if (valid) {
#pragma unroll 2
                    for (int e = r0; e < r1; e++) {
                        int src = __ldg(&g_es[e]);
                        float ee = g_p1[src] + p2d + battn;
                        ee = ee > 0.f ? ee : 0.2f * ee;
                        float ex = __expf(ee);
                        denom += ex;
                        float4 hv = __ldg((const float4*)(h + (size_t)src * H + lane * 4));
                        acc.x += ex * hv.x; acc.y += ex * hv.y;
                        acc.z += ex * hv.z; acc.w += ex * hv.w;
                    }
                }
                float act = 0.f, rd = 0.f;
                if (valid && denom > 0.f) { act = 1.f; rd = 1.f / (denom + 1e-16f); }
                int bh2 = n * ASTH + lane * 4;
                *(__half2*)&xs[bh2]     = __floats2half2_rn(acc.x * rd, acc.y * rd);
                *(__half2*)&xs[bh2 + 2] = __floats2half2_rn(acc.z * rd, acc.w * rd);
                float4 hv = *(const float4*)&h[(size_t)node * H + lane * 4];
                *(__half2*)&hs[bh2]     = __floats2half2_rn(hv.x, hv.y);
                *(__half2*)&hs[bh2 + 2] = __floats2half2_rn(hv.z, hv.w);
                *(float4*)&hsf[n * ASTF + lane * 4] = hv;
                if (lane == 0) { sact[n] = act; srd[n] = rd; }
            }
            // (mma_dual entry sync covers staging visibility)

            int ty_lo = 0, ty_hi = 0;
            float rr[4][4], zz[4][4];
            for (int chunk = 0; chunk < 3; chunk++) {
                float dx[4][4], dh[4][4];
#pragma unroll
                for (int f = 0; f < 4; f++)
#pragma unroll
                    for (int j = 0; j < 4; j++) { dx[f][j] = 0.f; dh[f][j] = 0.f; }
                mma_dual(dx, dh, chunk * H, xs, hs, wsA0, wsA1, wsB0, wsB1,
                         m0, nw32, grp, t4, t);
                if (chunk == 0) { ty_lo = stype[m0 + grp]; ty_hi = stype[m0 + grp + 8]; }
                int rb = chunk * H;
                if (chunk < 2) {
#pragma unroll
                    for (int f = 0; f < 4; f++) {
                        int feat0 = nw32 + (f << 3) + (t4 << 1);
                        float bb0 = sbb[rb + feat0],  bb1 = sbb[rb + feat0 + 1];
                        float bh0 = sbh[rb + feat0],  bh1 = sbh[rb + feat0 + 1];
                        float clo0 = smnt[ty_lo * 384 + rb + feat0];
                        float clo1 = smnt[ty_lo * 384 + rb + feat0 + 1];
                        float chi0 = smnt[ty_hi * 384 + rb + feat0];
                        float chi1 = smnt[ty_hi * 384 + rb + feat0 + 1];
                        float g0 = sig_(dx[f][0] + bb0 + clo0 + dh[f][0] + bh0);
                        float g1 = sig_(dx[f][1] + bb1 + clo1 + dh[f][1] + bh1);
                        float g2 = sig_(dx[f][2] + bb0 + chi0 + dh[f][2] + bh0);
                        float g3 = sig_(dx[f][3] + bb1 + chi1 + dh[f][3] + bh1);
                        if (chunk == 0) { rr[f][0]=g0; rr[f][1]=g1; rr[f][2]=g2; rr[f][3]=g3; }
                        else            { zz[f][0]=g0; zz[f][1]=g1; zz[f][2]=g2; zz[f][3]=g3; }
                    }
                } else {
                    int nl_lo = m0 + grp, nl_hi = m0 + grp + 8;
                    int node_lo = snode[nl_lo], node_hi = snode[nl_hi];
                    bool act_lo = sact[nl_lo] > 0.f, act_hi = sact[nl_hi] > 0.f;
                    float s1lo = 0.f, s2lo = 0.f, s1hi = 0.f, s2hi = 0.f;
#pragma unroll
                    for (int f = 0; f < 4; f++) {
                        int feat0 = nw32 + (f << 3) + (t4 << 1);
                        float bb0 = sbb[rb + feat0],  bb1 = sbb[rb + feat0 + 1];
                        float bh0 = sbh[rb + feat0],  bh1 = sbh[rb + feat0 + 1];
                        float clo0 = smnt[ty_lo * 384 + rb + feat0];
                        float clo1 = smnt[ty_lo * 384 + rb + feat0 + 1];
                        float chi0 = smnt[ty_hi * 384 + rb + feat0];
                        float chi1 = smnt[ty_hi * 384 + rb + feat0 + 1];
                        float n0 = tanh_(dx[f][0] + bb0 + clo0 + rr[f][0] * (dh[f][0] + bh0));
                        float n1 = tanh_(dx[f][1] + bb1 + clo1 + rr[f][1] * (dh[f][1] + bh1));
                        float n2 = tanh_(dx[f][2] + bb0 + chi0 + rr[f][2] * (dh[f][2] + bh0));
                        float n3 = tanh_(dx[f][3] + bb1 + chi1 + rr[f][3] * (dh[f][3] + bh1));
                        float ho0 = hsf[nl_lo * ASTF + feat0];
                        float ho1 = hsf[nl_lo * ASTF + feat0 + 1];
                        float ho2 = hsf[nl_hi * ASTF + feat0];
                        float ho3 = hsf[nl_hi * ASTF + feat0 + 1];
                        float v0 = (1.f - zz[f][0]) * n0 + zz[f][0] * ho0;
                        float v1 = (1.f - zz[f][1]) * n1 + zz[f][1] * ho1;
                        float v2 = (1.f - zz[f][2]) * n2 + zz[f][2] * ho2;
                        float v3 = (1.f - zz[f][3]) * n3 + zz[f][3] * ho3;
                        if (act_lo)
                            *(float2*)&h[(size_t)node_lo * H + feat0] = make_float2(v0, v1);
                        if (act_hi)
                            *(float2*)&h[(size_t)node_hi * H + feat0] = make_float2(v2, v3);
                        float2 wa1 = *(const float2*)&Wattn[feat0];
                        float2 wa2 = *(const float2*)&Wattn[H + feat0];
                        s1lo += v0 * wa1.x + v1 * wa1.y;
                        s2lo += v0 * wa2.x + v1 * wa2.y;
                        s1hi += v2 * wa1.x + v3 * wa1.y;
                        s2hi += v2 * wa2.x + v3 * wa2.y;
                    }
                    atomicAdd(&sp1[nl_lo], s1lo);
                    atomicAdd(&sp2[nl_lo], s2lo);
                    atomicAdd(&sp1[nl_hi], s1hi);
                    atomicAdd(&sp2[nl_hi], s2hi);
                }
            }
            __syncthreads();
            if (t < TILE_N && sact[t] > 0.f) {
                int node = snode[t];
                g_p1[node] = sp1[t];
                g_p2[node] = sp2[t];
            }
        }
        if (level < DEPTH - 1) gbar(3 + level, t);   // sync levels 1..6
    }
}

// ---------------- launch ----------------
extern "C" void kernel_launch(void* const* d_in, const int* in_sizes, int n_in,
                              void* d_out, int out_size) {
    const float* node_embedding = (const float*)d_in[0];
    const float* node_type      = (const float*)d_in[1];
    const float* W_attn         = (const float*)d_in[2];
    const float* b_attn         = (const float*)d_in[3];
    const float* W_msg          = (const float*)d_in[4];
    const float* b_msg          = (const float*)d_in[5];
    const float* W_ih           = (const float*)d_in[6];
    const float* W_hh           = (const float*)d_in[7];
    const float* b_ih           = (const float*)d_in[8];
    const float* b_hh           = (const float*)d_in[9];
    const int*   edge_src       = (const int*)d_in[10];
    const int*   edge_dst       = (const int*)d_in[11];
    const int*   fnl            = (const int*)d_in[12];
    float* h = (float*)d_out;

    cudaFuncSetAttribute(k_all, cudaFuncAttributeMaxDynamicSharedMemorySize, SMB_TOTAL);

    k_setup<<<384, 128>>>(W_ih, W_msg, b_ih, b_msg, W_hh);
    k_all<<<NBLOCKS, NTHREADS, SMB_TOTAL>>>(h, node_embedding, node_type,
                                            W_attn, b_attn, W_ih, b_hh,
                                            edge_src, edge_dst, fnl);
}

// round 14
// speedup vs baseline: 1.0805x; 1.0805x over previous
#include <cuda_runtime.h>
#include <cuda_fp16.h>
#include <cstdint>

#define N_NODES 50000
#define N_EDGES 400000
#define H 128
#define DEPTH 8
#define TILE_N 64      // nodes per block tile
#define NTHREADS 1024
#define NBLOCKS 148
#define ASTH 136       // activation smem row stride in halves (128 + 8)
#define WSTH 40        // weight slab row stride in halves (32 + 8)

// ---------------- device scratch (no allocation allowed) ----------------
__device__ float  g_p1[N_NODES];
__device__ float  g_p2[N_NODES];
__device__ int    g_node_list[N_NODES];
__device__ int    g_deg[N_NODES];
__device__ int    g_row[N_NODES + 1];
__device__ int    g_cur[N_NODES];
__device__ int    g_es[N_EDGES];          // edge srcs grouped by dst (CSR)
__device__ int    g_cnts[32];
__device__ int    g_node_off[DEPTH + 1];
__device__ unsigned g_bar_count;          // cumulative grid-barrier counter
__device__ unsigned g_base;               // snapshot at launch (k_setup)
// fused weights, ROW-major [384 rows][128 k], fp16
__device__ __half g_WbigH[384 * 128];     // W_ih[:,:128] @ W_msg
__device__ __half g_WhhH[384 * 128];
__device__ float  g_bbig[384];            // b_ih + W_ih[:,:128] @ b_msg

// smem byte offsets for k_all dynamic smem
#define SMB_WSA0  0                 // 128*40 halves = 10240 B
#define SMB_WSA1  10240
#define SMB_WSB0  20480
#define SMB_WSB1  30720
#define SMB_XS    40960             // 64*136 halves = 17408 B
#define SMB_HS    58368             // 17408 B
#define SMB_NT    75776             // 3*384 fp32 = 4608 B
#define SMB_BB    80384             // 1536 B
#define SMB_BH    81920             // 1536 B
#define SMB_SP1   83456             // 256 B
#define SMB_SP2   83712
#define SMB_SNODE 83968
#define SMB_SACT  84224
#define SMB_STYPE 84480
#define SMB_TOTAL 84736

__device__ __forceinline__ int clamp_lvl(int l) { return l < 0 ? 0 : (l > 7 ? 7 : l); }
__device__ __forceinline__ float sig_(float x) { return 1.0f / (1.0f + __expf(-x)); }
__device__ __forceinline__ float tanh_(float x) { return 2.0f / (1.0f + __expf(-2.0f * x)) - 1.0f; }

// software grid barrier: all 148 blocks co-resident (83KB smem, 1024 thr -> 1 block/SM).
__device__ __forceinline__ void gbar(int nb, int t) {
    __syncthreads();
    if (t == 0) {
        __threadfence();
        atomicAdd(&g_bar_count, 1u);
        unsigned target = g_base + (unsigned)nb * (unsigned)NBLOCKS;
        unsigned cur;
        do {
            asm volatile("ld.acquire.gpu.u32 %0, [%1];"
                         : "=r"(cur) : "l"(&g_bar_count) : "memory");
        } while ((int)(cur - target) < 0);
    }
    __syncthreads();
}

// ---------------- setup: fuse W_big + convert Whh + zero deg/cnts + base snapshot --
__global__ __launch_bounds__(128) void k_setup(const float* __restrict__ Wih,
                                               const float* __restrict__ Wmsg,
                                               const float* __restrict__ bih,
                                               const float* __restrict__ bmsg,
                                               const float* __restrict__ Whh) {
    int r = blockIdx.x;        // 0..383
    int m = threadIdx.x;       // 0..127
    if (r == 0 && m == 0) g_base = g_bar_count;   // snapshot for this launch
    __shared__ float wr[128];
    wr[m] = Wih[r * 131 + m];
    __syncthreads();
    float s = 0.f;
#pragma unroll 8
    for (int j = 0; j < 128; j++) s += wr[j] * Wmsg[j * 128 + m];
    g_WbigH[r * 128 + m] = __float2half(s);
    if (m == 0) {
        float b = bih[r];
        for (int j = 0; j < 128; j++) b += wr[j] * bmsg[j];
        g_bbig[r] = b;
    }
    int gid = r * 128 + m;                       // 0..49151
    g_WhhH[gid] = __float2half(Whh[gid]);
    for (int idx = gid; idx < N_NODES; idx += 384 * 128) g_deg[idx] = 0;
    if (gid < 32) g_cnts[gid] = 0;
}

// ---------------- weight slab prefetch ----------------
__device__ __forceinline__ void issue_dual(int rowBase, int k0,
                                           __half* bufA, __half* bufB, int t) {
    if (t < 512) {
        int row = t >> 2, seg = (t & 3) << 3;   // 512 threads cover 128 rows x 4 segs
        unsigned da = (unsigned)__cvta_generic_to_shared(bufA + row * WSTH + seg);
        const __half* sa = g_WbigH + (size_t)(rowBase + row) * 128 + k0 + seg;
        asm volatile("cp.async.cg.shared.global [%0],[%1],16;"
                     :: "r"(da), "l"(sa) : "memory");
        unsigned db = (unsigned)__cvta_generic_to_shared(bufB + row * WSTH + seg);
        const __half* sb = g_WhhH + (size_t)(rowBase + row) * 128 + k0 + seg;
        asm volatile("cp.async.cg.shared.global [%0],[%1],16;"
                     :: "r"(db), "l"(sb) : "memory");
    }
}

// dx += Wbig-chunk @ xs^T and dh += Whh-chunk @ hs^T, pipelined.
// warp: m0 nodes (16), nw16 rows (16): f loop = 2.
__device__ __forceinline__ void mma_dual(float (&dx)[2][4], float (&dh)[2][4],
                                         int rowBase,
                                         const __half* xs, const __half* hs,
                                         __half* wsA0, __half* wsA1,
                                         __half* wsB0, __half* wsB1,
                                         int m0, int nw16, int grp, int t4, int t) {
    __syncthreads();
    issue_dual(rowBase, 0, wsA0, wsB0, t);
    asm volatile("cp.async.commit_group;" ::: "memory");
    const unsigned* xu = (const unsigned*)xs;
    const unsigned* hu = (const unsigned*)hs;
#pragma unroll
    for (int s = 0; s < 4; s++) {
        asm volatile("cp.async.wait_group 0;" ::: "memory");
        __syncthreads();
        if (s < 3) {
            issue_dual(rowBase, (s + 1) << 5,
                       (s & 1) ? wsA0 : wsA1, (s & 1) ? wsB0 : wsB1, t);
            asm volatile("cp.async.commit_group;" ::: "memory");
        }
        const unsigned* ba = (const unsigned*)((s & 1) ? wsA1 : wsA0);
        const unsigned* bb = (const unsigned*)((s & 1) ? wsB1 : wsB0);
#pragma unroll
        for (int kstep = 0; kstep < 2; kstep++) {
            int aw = (m0 + grp) * (ASTH / 2) + (s << 4) + (kstep << 3) + t4;
            unsigned xa0 = xu[aw];
            unsigned xa1 = xu[aw + 8 * (ASTH / 2)];
            unsigned xa2 = xu[aw + 4];
            unsigned xa3 = xu[aw + 4 + 8 * (ASTH / 2)];
            unsigned ha0 = hu[aw];
            unsigned ha1 = hu[aw + 8 * (ASTH / 2)];
            unsigned ha2 = hu[aw + 4];
            unsigned ha3 = hu[aw + 4 + 8 * (ASTH / 2)];
#pragma unroll
            for (int f = 0; f < 2; f++) {
                int bw = (nw16 + (f << 3) + grp) * (WSTH / 2) + (kstep << 3) + t4;
                unsigned b0 = ba[bw];
                unsigned b1 = ba[bw + 4];
                asm volatile(
                    "mma.sync.aligned.m16n8k16.row.col.f32.f16.f16.f32 "
                    "{%0,%1,%2,%3},{%4,%5,%6,%7},{%8,%9},{%0,%1,%2,%3};"
                    : "+f"(dx[f][0]), "+f"(dx[f][1]), "+f"(dx[f][2]), "+f"(dx[f][3])
                    : "r"(xa0), "r"(xa1), "r"(xa2), "r"(xa3), "r"(b0), "r"(b1));
                unsigned c0 = bb[bw];
                unsigned c1 = bb[bw + 4];
                asm volatile(
                    "mma.sync.aligned.m16n8k16.row.col.f32.f16.f16.f32 "
                    "{%0,%1,%2,%3},{%4,%5,%6,%7},{%8,%9},{%0,%1,%2,%3};"
                    : "+f"(dh[f][0]), "+f"(dh[f][1]), "+f"(dh[f][2]), "+f"(dh[f][3])
                    : "r"(ha0), "r"(ha1), "r"(ha2), "r"(ha3), "r"(c0), "r"(c1));
            }
        }
    }
}

// ---------------- the persistent mega-kernel ----------------
__global__ __launch_bounds__(NTHREADS, 1) void k_all(
    float* __restrict__ h, const float* __restrict__ ne,
    const float* __restrict__ node_type,
    const float* __restrict__ Wattn, const float* __restrict__ b_attn,
    const float* __restrict__ Wih, const float* __restrict__ bhh,
    const int* __restrict__ esrc, const int* __restrict__ edst,
    const int* __restrict__ fnl) {
    extern __shared__ __align__(16) char smb[];
    __half* wsA0 = (__half*)(smb + SMB_WSA0);
    __half* wsA1 = (__half*)(smb + SMB_WSA1);
    __half* wsB0 = (__half*)(smb + SMB_WSB0);
    __half* wsB1 = (__half*)(smb + SMB_WSB1);
    __half* xs   = (__half*)(smb + SMB_XS);
    __half* hs   = (__half*)(smb + SMB_HS);
    float*  smnt = (float*)(smb + SMB_NT);
    float*  sbb  = (float*)(smb + SMB_BB);
    float*  sbh  = (float*)(smb + SMB_BH);
    float*  sp1  = (float*)(smb + SMB_SP1);
    float*  sp2  = (float*)(smb + SMB_SP2);
    int*    snode = (int*)(smb + SMB_SNODE);
    float*  sact  = (float*)(smb + SMB_SACT);
    int*    stype = (int*)(smb + SMB_STYPE);

    int t = threadIdx.x;
    int lane = t & 31;
    int warp = t >> 5;                // 0..31
    int gtid = blockIdx.x * NTHREADS + t;
    int gstride = NBLOCKS * NTHREADS;

    // ---- Phase A: degree count + level histogram ----
    {
        __shared__ int sc[8];
        if (t < 8) sc[t] = 0;
        __syncthreads();
        for (int i = gtid; i < N_EDGES; i += gstride)
            atomicAdd(&g_deg[__ldg(&edst[i])], 1);
        for (int i = gtid; i < N_NODES; i += gstride)
            atomicAdd(&sc[clamp_lvl(__ldg(&fnl[i]))], 1);
        __syncthreads();
        if (t < 8 && sc[t] > 0) atomicAdd(&g_cnts[t], sc[t]);
    }
    gbar(1, t);

    // ---- Phase B: block 0 scans levels + degrees ----
    if (blockIdx.x == 0) {
        __shared__ int wsum2[32];
        if (t == 0) {
            int no = 0;
            for (int l = 0; l < 8; l++) { g_node_off[l] = no; no += g_cnts[l]; }
            g_node_off[8] = no;
            for (int l = 0; l < 8; l++) g_cnts[16 + l] = g_node_off[l];
        }
        const int SP = 49;                        // 1024*49 >= 50000
        int base = t * SP;
        int s = 0;
        for (int j = 0; j < SP; j++) {
            int idx = base + j;
            if (idx < N_NODES) s += g_deg[idx];
        }
        int v = s;
#pragma unroll
        for (int off = 1; off < 32; off <<= 1) {
            int n = __shfl_up_sync(0xffffffffu, v, off);
            if (lane >= off) v += n;
        }
        if (lane == 31) wsum2[warp] = v;
        __syncthreads();
        if (warp == 0) {
            int wv = wsum2[lane];
#pragma unroll
            for (int off = 1; off < 32; off <<= 1) {
                int n = __shfl_up_sync(0xffffffffu, wv, off);
                if (lane >= off) wv += n;
            }
            wsum2[lane] = wv;
        }
        __syncthreads();
        int run = v - s + (warp > 0 ? wsum2[warp - 1] : 0);
        for (int j = 0; j < SP; j++) {
            int idx = base + j;
            if (idx < N_NODES) {
                g_row[idx] = run;
                g_cur[idx] = run;
                run += g_deg[idx];
            }
        }
        if (t == NTHREADS - 1) g_row[N_NODES] = run;
    }
    gbar(2, t);

    // ---- Phase C: node scatter + CSR edge fill + init h/p1/p2 ----
    {
        __shared__ int scnt[8];
        __shared__ int sbase[8];
        if (t < 8) scnt[t] = 0;
        __syncthreads();
        int i = gtid;                  // 151552 threads >= 50000 nodes: one chunk
        int key = -1, lp = 0;
        if (i < N_NODES) {
            key = clamp_lvl(__ldg(&fnl[i]));
            lp = atomicAdd(&scnt[key], 1);
        }
        __syncthreads();
        if (t < 8 && scnt[t] > 0) sbase[t] = atomicAdd(&g_cnts[16 + t], scnt[t]);
        __syncthreads();
        if (key >= 0) g_node_list[sbase[key] + lp] = i;

        for (int e = gtid; e < N_EDGES; e += gstride) {
            int d = __ldg(&edst[e]);
            int pos = atomicAdd(&g_cur[d], 1);
            g_es[pos] = __ldg(&esrc[e]);
        }

        float4 a1 = *(const float4*)&Wattn[lane * 4];
        float4 a2 = *(const float4*)&Wattn[H + lane * 4];
        int gw = blockIdx.x * 32 + warp;
        int nwr = NBLOCKS * 32;
        for (int n = gw; n < N_NODES; n += nwr) {
            float4 v = *(const float4*)&ne[(size_t)n * H + lane * 4];
            *(float4*)&h[(size_t)n * H + lane * 4] = v;
            float s1 = v.x * a1.x + v.y * a1.y + v.z * a1.z + v.w * a1.w;
            float s2 = v.x * a2.x + v.y * a2.y + v.z * a2.z + v.w * a2.w;
#pragma unroll
            for (int off = 16; off; off >>= 1) {
                s1 += __shfl_xor_sync(0xffffffffu, s1, off);
                s2 += __shfl_xor_sync(0xffffffffu, s2, off);
            }
            if (lane == 0) { g_p1[n] = s1; g_p2[n] = s2; }
        }
    }
    gbar(3, t);

    // ---- Phase D: 7 fused gather+GRU levels ----
    int grp = lane >> 2;              // 0..7
    int t4 = lane & 3;                // 0..3
    int m0 = (warp & 3) << 4;         // node base within tile
    int nw16 = (warp >> 2) << 4;      // row base within chunk: 0..112
    float battn = __ldg(b_attn);

    // stage constants ONCE
    for (int idx = t; idx < 1152; idx += NTHREADS) {
        int c = idx % 3, r = idx / 3;
        smnt[c * 384 + r] = Wih[r * 131 + 128 + c];
    }
    for (int idx = t; idx < 384; idx += NTHREADS) {
        sbb[idx] = g_bbig[idx];
        sbh[idx] = bhh[idx];
    }

    for (int level = 1; level < DEPTH; level++) {
        int start = g_node_off[level], end = g_node_off[level + 1];
        int cnt = end - start;
        int ntiles = (cnt + TILE_N - 1) / TILE_N;

        for (int tile = blockIdx.x; tile < ntiles; tile += NBLOCKS) {
            __syncthreads();
            if (t < TILE_N) {
                int slot = start + tile * TILE_N + t;
                int node = -1, ty = 0;
                if (slot < end) {
                    node = g_node_list[slot];
                    float n1 = node_type[(size_t)node * 3 + 1];
                    float n2 = node_type[(size_t)node * 3 + 2];
                    ty = n1 > 0.5f ? 1 : (n2 > 0.5f ? 2 : 0);
                }
                snode[t] = node; stype[t] = ty;
                sp1[t] = 0.f; sp2[t] = 0.f;
            }
            __syncthreads();

            // latency-flat gather: warp w handles nodes 2w, 2w+1
#pragma unroll
            for (int j = 0; j < 2; j++) {
                int n = (warp << 1) | j;
                int nodeRaw = snode[n];
                bool valid = nodeRaw >= 0;
                int node = valid ? nodeRaw : 0;
                int r0 = g_row[node];
                int deg = valid ? (g_row[node + 1] - r0) : 0;
                float p2d = g_p2[node];
                float denom = 0.f;
                float4 acc = make_float4(0.f, 0.f, 0.f, 0.f);
                for (int base = 0; base < deg; base += 32) {
                    int m = deg - base; if (m > 32) m = 32;
                    float ex = 0.f; int src = 0;
                    if (lane < m) {
                        src = __ldg(&g_es[r0 + base + lane]);
                        float ee = g_p1[src] + p2d + battn;
                        ee = ee > 0.f ? ee : 0.2f * ee;
                        ex = __expf(ee);
                    }
                    float srd_ = ex;
#pragma unroll
                    for (int off = 16; off; off >>= 1)
                        srd_ += __shfl_xor_sync(0xffffffffu, srd_, off);
                    denom += srd_;
                    int q = 0;
                    for (; q + 4 <= m; q += 4) {      // MLP=4 gather
                        float e0 = __shfl_sync(0xffffffffu, ex, q);
                        float e1 = __shfl_sync(0xffffffffu, ex, q + 1);
                        float e2 = __shfl_sync(0xffffffffu, ex, q + 2);
                        float e3 = __shfl_sync(0xffffffffu, ex, q + 3);
                        int s0 = __shfl_sync(0xffffffffu, src, q);
                        int s1 = __shfl_sync(0xffffffffu, src, q + 1);
                        int s2 = __shfl_sync(0xffffffffu, src, q + 2);
                        int s3 = __shfl_sync(0xffffffffu, src, q + 3);
                        float4 h0 = __ldg((const float4*)(h + (size_t)s0 * H + lane * 4));
                        float4 h1 = __ldg((const float4*)(h + (size_t)s1 * H + lane * 4));
                        float4 h2 = __ldg((const float4*)(h + (size_t)s2 * H + lane * 4));
                        float4 h3 = __ldg((const float4*)(h + (size_t)s3 * H + lane * 4));
                        acc.x += e0 * h0.x + e1 * h1.x + e2 * h2.x + e3 * h3.x;
                        acc.y += e0 * h0.y + e1 * h1.y + e2 * h2.y + e3 * h3.y;
                        acc.z += e0 * h0.z + e1 * h1.z + e2 * h2.z + e3 * h3.z;
                        acc.w += e0 * h0.w + e1 * h1.w + e2 * h2.w + e3 * h3.w;
                    }
                    for (; q < m; q++) {
                        float eq = __shfl_sync(0xffffffffu, ex, q);
                        int sq = __shfl_sync(0xffffffffu, src, q);
                        float4 hv = __ldg((const float4*)(h + (size_t)sq * H + lane * 4));
                        acc.x += eq * hv.x; acc.y += eq * hv.y;
                        acc.z += eq * hv.z; acc.w += eq * hv.w;
                    }
                }
                float act = 0.f, rd = 0.f;
                if (valid && denom > 0.f) { act = 1.f; rd = 1.f / (denom + 1e-16f); }
                int bh2 = n * ASTH + lane * 4;
                *(__half2*)&xs[bh2]     = __floats2half2_rn(acc.x * rd, acc.y * rd);
                *(__half2*)&xs[bh2 + 2] = __floats2half2_rn(acc.z * rd, acc.w * rd);
                float4 hv = *(const float4*)&h[(size_t)node * H + lane * 4];
                *(__half2*)&hs[bh2]     = __floats2half2_rn(hv.x, hv.y);
                *(__half2*)&hs[bh2 + 2] = __floats2half2_rn(hv.z, hv.w);
                if (lane == 0) sact[n] = act;
            }
            // (mma_dual entry sync covers staging visibility)

            int ty_lo = 0, ty_hi = 0;
            float rr[2][4], zz[2][4];
            for (int chunk = 0; chunk < 3; chunk++) {
                float dx[2][4], dh[2][4];
#pragma unroll
                for (int f = 0; f < 2; f++)
#pragma unroll
                    for (int j = 0; j < 4; j++) { dx[f][j] = 0.f; dh[f][j] = 0.f; }
                mma_dual(dx, dh, chunk * H, xs, hs, wsA0, wsA1, wsB0, wsB1,
                         m0, nw16, grp, t4, t);
                if (chunk == 0) { ty_lo = stype[m0 + grp]; ty_hi = stype[m0 + grp + 8]; }
                int rb = chunk * H;
                if (chunk < 2) {
#pragma unroll
                    for (int f = 0; f < 2; f++) {
                        int feat0 = nw16 + (f << 3) + (t4 << 1);
                        float bb0 = sbb[rb + feat0],  bb1 = sbb[rb + feat0 + 1];
                        float bh0 = sbh[rb + feat0],  bh1 = sbh[rb + feat0 + 1];
                        float clo0 = smnt[ty_lo * 384 + rb + feat0];
                        float clo1 = smnt[ty_lo * 384 + rb + feat0 + 1];
                        float chi0 = smnt[ty_hi * 384 + rb + feat0];
                        float chi1 = smnt[ty_hi * 384 + rb + feat0 + 1];
                        float g0 = sig_(dx[f][0] + bb0 + clo0 + dh[f][0] + bh0);
                        float g1 = sig_(dx[f][1] + bb1 + clo1 + dh[f][1] + bh1);
                        float g2 = sig_(dx[f][2] + bb0 + chi0 + dh[f][2] + bh0);
                        float g3 = sig_(dx[f][3] + bb1 + chi1 + dh[f][3] + bh1);
                        if (chunk == 0) { rr[f][0]=g0; rr[f][1]=g1; rr[f][2]=g2; rr[f][3]=g3; }
                        else            { zz[f][0]=g0; zz[f][1]=g1; zz[f][2]=g2; zz[f][3]=g3; }
                    }
                } else {
                    int nl_lo = m0 + grp, nl_hi = m0 + grp + 8;
                    int node_lo = snode[nl_lo], node_hi = snode[nl_hi];
                    bool act_lo = sact[nl_lo] > 0.f, act_hi = sact[nl_hi] > 0.f;
                    float s1lo = 0.f, s2lo = 0.f, s1hi = 0.f, s2hi = 0.f;
#pragma unroll
                    for (int f = 0; f < 2; f++) {
                        int feat0 = nw16 + (f << 3) + (t4 << 1);
                        float bb0 = sbb[rb + feat0],  bb1 = sbb[rb + feat0 + 1];
                        float bh0 = sbh[rb + feat0],  bh1 = sbh[rb + feat0 + 1];
                        float clo0 = smnt[ty_lo * 384 + rb + feat0];
                        float clo1 = smnt[ty_lo * 384 + rb + feat0 + 1];
                        float chi0 = smnt[ty_hi * 384 + rb + feat0];
                        float chi1 = smnt[ty_hi * 384 + rb + feat0 + 1];
                        float n0 = tanh_(dx[f][0] + bb0 + clo0 + rr[f][0] * (dh[f][0] + bh0));
                        float n1 = tanh_(dx[f][1] + bb1 + clo1 + rr[f][1] * (dh[f][1] + bh1));
                        float n2 = tanh_(dx[f][2] + bb0 + chi0 + rr[f][2] * (dh[f][2] + bh0));
                        float n3 = tanh_(dx[f][3] + bb1 + chi1 + rr[f][3] * (dh[f][3] + bh1));
                        float2 hlo = *(const float2*)&h[(size_t)node_lo * H + feat0];
                        float2 hhi = *(const float2*)&h[(size_t)node_hi * H + feat0];
                        float v0 = (1.f - zz[f][0]) * n0 + zz[f][0] * hlo.x;
                        float v1 = (1.f - zz[f][1]) * n1 + zz[f][1] * hlo.y;
                        float v2 = (1.f - zz[f][2]) * n2 + zz[f][2] * hhi.x;
                        float v3 = (1.f - zz[f][3]) * n3 + zz[f][3] * hhi.y;
                        if (act_lo)
                            *(float2*)&h[(size_t)node_lo * H + feat0] = make_float2(v0, v1);
                        if (act_hi)
                            *(float2*)&h[(size_t)node_hi * H + feat0] = make_float2(v2, v3);
                        float2 wa1 = *(const float2*)&Wattn[feat0];
                        float2 wa2 = *(const float2*)&Wattn[H + feat0];
                        s1lo += v0 * wa1.x + v1 * wa1.y;
                        s2lo += v0 * wa2.x + v1 * wa2.y;
                        s1hi += v2 * wa1.x + v3 * wa1.y;
                        s2hi += v2 * wa2.x + v3 * wa2.y;
                    }
                    atomicAdd(&sp1[nl_lo], s1lo);
                    atomicAdd(&sp2[nl_lo], s2lo);
                    atomicAdd(&sp1[nl_hi], s1hi);
                    atomicAdd(&sp2[nl_hi], s2hi);
                }
            }
            __syncthreads();
            if (t < TILE_N && sact[t] > 0.f) {
                int node = snode[t];
                g_p1[node] = sp1[t];
                g_p2[node] = sp2[t];
            }
        }
        if (level < DEPTH - 1) gbar(3 + level, t);   // sync levels 1..6
    }
}

// ---------------- launch ----------------
extern "C" void kernel_launch(void* const* d_in, const int* in_sizes, int n_in,
                              void* d_out, int out_size) {
    const float* node_embedding = (const float*)d_in[0];
    const float* node_type      = (const float*)d_in[1];
    const float* W_attn         = (const float*)d_in[2];
    const float* b_attn         = (const float*)d_in[3];
    const float* W_msg          = (const float*)d_in[4];
    const float* b_msg          = (const float*)d_in[5];
    const float* W_ih           = (const float*)d_in[6];
    const float* W_hh           = (const float*)d_in[7];
    const float* b_ih           = (const float*)d_in[8];
    const float* b_hh           = (const float*)d_in[9];
    const int*   edge_src       = (const int*)d_in[10];
    const int*   edge_dst       = (const int*)d_in[11];
    const int*   fnl            = (const int*)d_in[12];
    float* h = (float*)d_out;

    cudaFuncSetAttribute(k_all, cudaFuncAttributeMaxDynamicSharedMemorySize, SMB_TOTAL);

    k_setup<<<384, 128>>>(W_ih, W_msg, b_ih, b_msg, W_hh);
    k_all<<<NBLOCKS, NTHREADS, SMB_TOTAL>>>(h, node_embedding, node_type,
                                            W_attn, b_attn, W_ih, b_hh,
                                            edge_src, edge_dst, fnl);
}